// round 1
// baseline (speedup 1.0000x reference)
#include <cuda_runtime.h>

#define BB 16
#define TT 2048
#define DD 512
#define BD 64
#define NREC 196   // k(64) v(64) q(64) eta(1) pad(3) -> 49 float4

// scratch (static device globals: allocation-guard safe)
__device__ float g_proj[(size_t)BB * TT * NREC];   // ~25.7 MB
__device__ float g_h[(size_t)BB * TT * BD];        // ~8.4 MB

typedef unsigned long long ull;

__device__ __forceinline__ ull pack2(float a, float b) {
    ull r; asm("mov.b64 %0, {%1, %2};" : "=l"(r) : "f"(a), "f"(b)); return r;
}
__device__ __forceinline__ void unpack2(ull v, float& a, float& b) {
    asm("mov.b64 {%0, %1}, %2;" : "=f"(a), "=f"(b) : "l"(v));
}
__device__ __forceinline__ void fma2(ull& d, ull a, ull b) {
    asm("fma.rn.f32x2 %0, %1, %2, %0;" : "+l"(d) : "l"(a), "l"(b));
}

// ---------------------------------------------------------------------------
// Kernel 1: projections  proj[bt][0:64)=k, [64:128)=v, [128:192)=q, [192]=eta
// GEMM: M=32768 (B*T), N=196(pad 208), K=512.  BM=64, full N per CTA.
// ---------------------------------------------------------------------------
__global__ void __launch_bounds__(256) proj_kernel(
    const float* __restrict__ x,
    const float* __restrict__ Wk, const float* __restrict__ bk,
    const float* __restrict__ Wv, const float* __restrict__ bv,
    const float* __restrict__ Wq, const float* __restrict__ bq,
    const float* __restrict__ lr_w, const float* __restrict__ lr_b)
{
    __shared__ float sx[32][65];    // [k][m], padded
    __shared__ float sw[32][208];   // [k][n], n padded to 208

    const int tid = threadIdx.x;
    const int mbase = blockIdx.x * 64;
    const int m  = tid >> 2;          // 0..63
    const int ng = tid & 3;
    const int c0 = ng * 52;           // 52 cols per thread, 16B aligned

    ull acc[26];
#pragma unroll
    for (int j = 0; j < 26; j++) acc[j] = 0ull;

    for (int kb = 0; kb < DD; kb += 32) {
        __syncthreads();
        // x tile: 64 m x 32 k = 512 float4, 2 per thread, store transposed
        {
            int t4 = tid;
#pragma unroll
            for (int it = 0; it < 2; it++, t4 += 256) {
                int mm = t4 >> 3;
                int kg = (t4 & 7) * 4;
                float4 v = *(const float4*)&x[(size_t)(mbase + mm) * DD + kb + kg];
                sx[kg + 0][mm] = v.x; sx[kg + 1][mm] = v.y;
                sx[kg + 2][mm] = v.z; sx[kg + 3][mm] = v.w;
            }
        }
        // W tile 32 x 208 (concat Wk|Wv|Wq|lr_w|0)
        for (int idx = tid; idx < 32 * 208; idx += 256) {
            int kk = idx / 208, n = idx % 208;
            int krow = kb + kk;
            float v;
            if      (n < 64)  v = Wk[krow * 64 + n];
            else if (n < 128) v = Wv[krow * 64 + (n - 64)];
            else if (n < 192) v = Wq[krow * 64 + (n - 128)];
            else if (n == 192) v = lr_w[krow];
            else v = 0.f;
            sw[kk][n] = v;
        }
        __syncthreads();
#pragma unroll 4
        for (int k = 0; k < 32; k++) {
            float xv = sx[k][m];
            ull xp = pack2(xv, xv);
#pragma unroll
            for (int j = 0; j < 13; j++) {
                float4 w4 = *(const float4*)&sw[k][c0 + 4 * j];
                fma2(acc[2 * j + 0], xp, pack2(w4.x, w4.y));
                fma2(acc[2 * j + 1], xp, pack2(w4.z, w4.w));
            }
        }
    }
    // epilogue: biases + sigmoid(eta)
    float out[52];
#pragma unroll
    for (int j = 0; j < 26; j++) unpack2(acc[j], out[2 * j], out[2 * j + 1]);
    float* dst = &g_proj[(size_t)(mbase + m) * NREC];
    float lb0 = lr_b[0];
#pragma unroll
    for (int j = 0; j < 52; j++) {
        int n = c0 + j;
        if (n >= NREC) break;
        float v = out[j];
        if      (n < 64)   v += bk[n];
        else if (n < 128)  v += bv[n - 64];
        else if (n < 192)  v += bq[n - 128];
        else if (n == 192) v = 1.f / (1.f + expf(-(v + lb0)));
        dst[n] = v;
    }
}

// ---------------------------------------------------------------------------
// Kernel 2: sequential TTT scan. 1 CTA per batch, 128 threads.
// Thread (o = tid>>1, h = tid&1) owns W[o][32h .. 32h+31] as 16 f32x2 regs.
// Rank-1 gradient: gW = gz (x) k ; (W_new) q = W q - eta*(k.q)*gz.
// Merged LN1-backward reductions via a = g*(k - v + ln_b), c = g^2.
// ---------------------------------------------------------------------------
__global__ void __launch_bounds__(128) scan_kernel(
    const float* __restrict__ W0,
    const float* __restrict__ ln_g, const float* __restrict__ ln_b)
{
    __shared__ float sbuf[2][NREC];
    __shared__ float sredA[7][4];
    __shared__ float sredB[2][4];
    __shared__ float tmp4[4];

    const int b    = blockIdx.x;
    const int tid  = threadIdx.x;
    const int o    = tid >> 1;
    const int h    = tid & 1;
    const int wid  = tid >> 5;
    const int lane = tid & 31;

    const float go = ln_g[o];
    const float lb = ln_b[o];
    const float co = go * go;

    // Sc = sum_o g_o^2 (constant)
    float Sc;
    {
        float v = co;
#pragma unroll
        for (int off = 16; off; off >>= 1) v += __shfl_xor_sync(0xffffffffu, v, off);
        if (lane == 0) tmp4[wid] = v;
        __syncthreads();
        Sc = 0.5f * (tmp4[0] + tmp4[1] + tmp4[2] + tmp4[3]);  // each row counted twice
        __syncthreads();
    }

    // W half-row in registers (f32x2)
    ull w[16];
    {
        const float* wr = &W0[o * 64 + 32 * h];
#pragma unroll
        for (int j = 0; j < 16; j++) w[j] = *(const ull*)&wr[2 * j];
    }

    const float* proj = &g_proj[(size_t)b * TT * NREC];
    float* hout = &g_h[(size_t)b * TT * BD];

    // preload token 0; issue LDG for token 1
    float4 pv = make_float4(0.f, 0.f, 0.f, 0.f);
    if (tid < 49) {
        *(float4*)&sbuf[0][tid * 4] = *(const float4*)&proj[tid * 4];
        pv = *(const float4*)&proj[(size_t)NREC + tid * 4];
    }
    __syncthreads();

    const float inv128 = 1.f / 128.f;
    const float twon = 2.f / 64.f;
    const float mean_c = Sc * (1.f / 64.f);

    for (int t = 0; t < TT; t++) {
        const int cur = t & 1;
        const float* kbuf = &sbuf[cur][0];
        const float* vbuf = &sbuf[cur][64];
        const float* qbuf = &sbuf[cur][128];
        const float eta = sbuf[cur][192];

        // prefetch pipeline: store token t+1 (loaded last iter), issue LDG t+2
        if (tid < 49) {
            if (t + 1 < TT) *(float4*)&sbuf[cur ^ 1][tid * 4] = pv;
            if (t + 2 < TT) pv = *(const float4*)&proj[(size_t)(t + 2) * NREC + tid * 4];
        }

        // load k,q halves into regs (reused for W update)
        ull kreg[16], qreg[16];
#pragma unroll
        for (int j = 0; j < 16; j++) {
            kreg[j] = *(const ull*)&kbuf[32 * h + 2 * j];
            qreg[j] = *(const ull*)&qbuf[32 * h + 2 * j];
        }
        // matvec: Z = W k, Zq = W q, kq partial
        ull zk2 = 0ull, zq2 = 0ull, kq2 = 0ull;
#pragma unroll
        for (int j = 0; j < 16; j++) {
            fma2(zk2, w[j], kreg[j]);
            fma2(zq2, w[j], qreg[j]);
            fma2(kq2, kreg[j], qreg[j]);
        }
        float ax, bx;
        unpack2(zk2, ax, bx); float Z   = ax + bx;
        unpack2(zq2, ax, bx); float Zq  = ax + bx;
        unpack2(kq2, ax, bx); float kqp = ax + bx;
        Z  += __shfl_xor_sync(0xffffffffu, Z, 1);   // full row dot (dup in pair)
        Zq += __shfl_xor_sync(0xffffffffu, Zq, 1);

        const float ko = kbuf[o], vo = vbuf[o], qo = qbuf[o];
        const float a = go * (ko - vo + lb);

        // single merged reduction round: {Z, Z^2, aZ, cZ, cZ^2, a, kq-partial}
        float r[7];
        r[0] = Z; r[1] = Z * Z; r[2] = a * Z; r[3] = co * Z; r[4] = co * Z * Z;
        r[5] = a; r[6] = kqp;
#pragma unroll
        for (int off = 16; off; off >>= 1) {
#pragma unroll
            for (int i = 0; i < 7; i++) r[i] += __shfl_xor_sync(0xffffffffu, r[i], off);
        }
        if (lane == 0) {
#pragma unroll
            for (int i = 0; i < 7; i++) sredA[i][wid] = r[i];
        }
        __syncthreads();
        float S[7];
#pragma unroll
        for (int i = 0; i < 7; i++) {
            float4 s4 = *(const float4*)&sredA[i][0];
            S[i] = (s4.x + s4.y) + (s4.z + s4.w);
        }
        // scalars (rows are double-counted -> /128 gives mean over 64)
        const float mu = S[0] * inv128;
        const float var = S[1] * inv128 - mu * mu;
        const float rs = rsqrtf(var + 1e-6f);
        const float mean_aZ  = S[2] * inv128;
        const float mean_cZ  = S[3] * inv128;
        const float mean_cZ2 = S[4] * inv128;
        const float mean_a   = S[5] * inv128;
        const float kq = S[6] * (1.f / 64.f);

        const float m1 = twon * (mean_a + rs * (mean_cZ - mu * mean_c));
        const float m2 = twon * (rs * (mean_aZ - mu * mean_a)
                       + rs * rs * (mean_cZ2 - 2.f * mu * mean_cZ + mu * mu * mean_c));
        const float zh = (Z - mu) * rs;
        const float ge = twon * (a + co * zh);
        const float gz = rs * (ge - m1 - zh * m2);
        const float coef = eta * gz;

        // rank-1 update: W[o][i] -= coef * k[i]
        ull nc = pack2(-coef, -coef);
#pragma unroll
        for (int j = 0; j < 16; j++) fma2(w[j], nc, kreg[j]);

        // corrected q matvec on W_new, then LN2
        const float Zqn = Zq - coef * kq;
        float s0 = Zqn, s1 = Zqn * Zqn;
#pragma unroll
        for (int off = 16; off; off >>= 1) {
            s0 += __shfl_xor_sync(0xffffffffu, s0, off);
            s1 += __shfl_xor_sync(0xffffffffu, s1, off);
        }
        if (lane == 0) { sredB[0][wid] = s0; sredB[1][wid] = s1; }
        __syncthreads();
        float4 b0 = *(const float4*)&sredB[0][0];
        float4 b1 = *(const float4*)&sredB[1][0];
        const float mu2 = ((b0.x + b0.y) + (b0.z + b0.w)) * inv128;
        const float e2  = ((b1.x + b1.y) + (b1.z + b1.w)) * inv128;
        const float rs2 = rsqrtf(e2 - mu2 * mu2 + 1e-6f);
        if (h == 0) {
            hout[(size_t)t * BD + o] = qo + (Zqn - mu2) * rs2 * go + lb;
        }
        // roundB barrier above orders sbuf/sredA reuse for next iteration
    }
}

// ---------------------------------------------------------------------------
// Kernel 3: z = h @ Wo + bo.  M=32768, K=64, N=512. BM=64, BN=64.
// ---------------------------------------------------------------------------
__global__ void __launch_bounds__(256) out_kernel(
    const float* __restrict__ Wo, const float* __restrict__ bo,
    float* __restrict__ z)
{
    __shared__ float sh[64][65];   // h tile [m][k], padded
    __shared__ float sw2[64][64];  // Wo tile [k][n]

    const int tid = threadIdx.x;
    const int mbase = blockIdx.x * 64;
    const int nbase = blockIdx.y * 64;
    const int m  = tid >> 2;
    const int ng = tid & 3;
    const int nc0 = ng * 16;

    // load tiles: 1024 float4 each, 4 per thread
    for (int i4 = tid; i4 < 1024; i4 += 256) {
        int row = i4 >> 4;
        int c = (i4 & 15) * 4;
        float4 v = *(const float4*)&g_h[(size_t)(mbase + row) * BD + c];
        sh[row][c] = v.x; sh[row][c + 1] = v.y; sh[row][c + 2] = v.z; sh[row][c + 3] = v.w;
        float4 wv = *(const float4*)&Wo[(size_t)row * DD + nbase + c];
        *(float4*)&sw2[row][c] = wv;
    }
    __syncthreads();

    ull acc[8];
#pragma unroll
    for (int j = 0; j < 8; j++) acc[j] = 0ull;
#pragma unroll 8
    for (int k = 0; k < 64; k++) {
        float hv = sh[m][k];
        ull hp = pack2(hv, hv);
        const float* wr = &sw2[k][nc0];
#pragma unroll
        for (int j = 0; j < 4; j++) {
            float4 w4 = *(const float4*)&wr[4 * j];
            fma2(acc[2 * j + 0], hp, pack2(w4.x, w4.y));
            fma2(acc[2 * j + 1], hp, pack2(w4.z, w4.w));
        }
    }
    float out[16];
#pragma unroll
    for (int j = 0; j < 8; j++) unpack2(acc[j], out[2 * j], out[2 * j + 1]);
    float* dst = &z[(size_t)(mbase + m) * DD + nbase + nc0];
#pragma unroll
    for (int j = 0; j < 16; j++) out[j] += bo[nbase + nc0 + j];
#pragma unroll
    for (int j4 = 0; j4 < 4; j4++) {
        *(float4*)&dst[4 * j4] = make_float4(out[4 * j4], out[4 * j4 + 1],
                                             out[4 * j4 + 2], out[4 * j4 + 3]);
    }
}

// ---------------------------------------------------------------------------
extern "C" void kernel_launch(void* const* d_in, const int* in_sizes, int n_in,
                              void* d_out, int out_size)
{
    const float* x    = (const float*)d_in[0];
    const float* Wk   = (const float*)d_in[1];
    const float* bk   = (const float*)d_in[2];
    const float* Wv   = (const float*)d_in[3];
    const float* bv   = (const float*)d_in[4];
    const float* Wq   = (const float*)d_in[5];
    const float* bq   = (const float*)d_in[6];
    const float* Wo   = (const float*)d_in[7];
    const float* bo   = (const float*)d_in[8];
    const float* ln_g = (const float*)d_in[9];
    const float* ln_b = (const float*)d_in[10];
    const float* lr_w = (const float*)d_in[11];
    const float* lr_b = (const float*)d_in[12];
    const float* W0   = (const float*)d_in[13];
    float* z = (float*)d_out;

    proj_kernel<<<512, 256>>>(x, Wk, bk, Wv, bv, Wq, bq, lr_w, lr_b);
    scan_kernel<<<BB, 128>>>(W0, ln_g, ln_b);
    out_kernel<<<dim3(512, 8), 256>>>(Wo, bo, z);
}

// round 3
// speedup vs baseline: 1.4389x; 1.4389x over previous
#include <cuda_runtime.h>

#define BB 16
#define TT 2048
#define DD 512
#define BD 64
#define NREC 256   // padded row: k(64) v(64) q(64) eta@192, pad to 256

// scratch (static device globals: allocation-guard safe)
__device__ float g_proj[(size_t)BB * TT * NREC];   // 33.5 MB
__device__ float g_h[(size_t)BB * TT * BD];        // 8.4 MB
__device__ float g_wcat[512 * 224];
__device__ float g_bcat[224];

typedef unsigned long long ull;

__device__ __forceinline__ ull pack2(float a, float b) {
    ull r; asm("mov.b64 %0, {%1, %2};" : "=l"(r) : "f"(a), "f"(b)); return r;
}
__device__ __forceinline__ void unpack2(ull v, float& a, float& b) {
    asm("mov.b64 {%0, %1}, %2;" : "=f"(a), "=f"(b) : "l"(v));
}
__device__ __forceinline__ void fma2(ull& d, ull a, ull b) {
    asm("fma.rn.f32x2 %0, %1, %2, %0;" : "+l"(d) : "l"(a), "l"(b));
}
__device__ __forceinline__ unsigned smem_u32(const void* p) {
    return (unsigned)__cvta_generic_to_shared(p);
}
__device__ __forceinline__ void cp16(unsigned dst, const void* src) {
    asm volatile("cp.async.cg.shared.global [%0], [%1], 16;" :: "r"(dst), "l"(src));
}
__device__ __forceinline__ void cp_commit() { asm volatile("cp.async.commit_group;"); }
template<int N> __device__ __forceinline__ void cp_wait() {
    asm volatile("cp.async.wait_group %0;" :: "n"(N));
}

// ---------------------------------------------------------------------------
// Kernel 0: pack Wcat[512][224] = [Wk|Wv|Wq|lr_w|pad], bcat[224]
// ---------------------------------------------------------------------------
__global__ void prep_kernel(
    const float* __restrict__ Wk, const float* __restrict__ Wv,
    const float* __restrict__ Wq, const float* __restrict__ lr_w,
    const float* __restrict__ bk, const float* __restrict__ bv,
    const float* __restrict__ bq)
{
    int idx = blockIdx.x * 256 + threadIdx.x;
    if (idx >= 512 * 224) return;
    int r = idx / 224, n = idx % 224;
    float v = 0.f;
    if      (n < 64)   v = Wk[r * 64 + n];
    else if (n < 128)  v = Wv[r * 64 + n - 64];
    else if (n < 192)  v = Wq[r * 64 + n - 128];
    else if (n == 192) v = lr_w[r];
    g_wcat[idx] = v;
    if (r == 0) {
        float bvv = 0.f;
        if      (n < 64)  bvv = bk[n];
        else if (n < 128) bvv = bv[n - 64];
        else if (n < 192) bvv = bq[n - 128];
        g_bcat[n] = bvv;
    }
}

// ---------------------------------------------------------------------------
// Kernel 1: proj = x @ Wcat.  M=32768, K=512, Ntile=112 (grid.y=2), BM=64.
// cp.async double-buffered; ulonglong2 smem reads feed f32x2 FMAs directly.
// ---------------------------------------------------------------------------
__global__ void __launch_bounds__(256) proj_kernel(
    const float* __restrict__ x, const float* __restrict__ lr_b)
{
    __shared__ float sx[2][64][36];    // [buf][m][k] 18432 B
    __shared__ float sw[2][32][112];   // [buf][k][n] 28672 B

    const int tid   = threadIdx.x;
    const int mbase = blockIdx.x * 64;
    const int half  = blockIdx.y;
    const int m  = tid >> 2;
    const int ng = tid & 3;
    const int c0 = ng * 28;            // 28 cols/thread; byte off 112*ng (16B-mult)

    // cp.async thread mapping
    const int xr = tid >> 2, xq = tid & 3;        // x: row 0..63, f4-col {xq, xq+4}
    const int wr = tid >> 3, wq = tid & 7;        // w: row 0..31, f4-col {wq+8i | <28}
    const float* xg = x + (size_t)(mbase + xr) * DD;
    const float* wg = g_wcat + (size_t)wr * 224 + half * 112;

    ull acc[14];
#pragma unroll
    for (int j = 0; j < 14; j++) acc[j] = 0ull;

    auto issue_tile = [&](int kb, int buf) {
        cp16(smem_u32(&sx[buf][xr][4 * xq]),       xg + kb + 4 * xq);
        cp16(smem_u32(&sx[buf][xr][4 * (xq + 4)]), xg + kb + 4 * (xq + 4));
#pragma unroll
        for (int i = 0; i < 4; i++) {
            int c = wq + 8 * i;                    // 28 f4 per 112-float row
            if (c < 28)
                cp16(smem_u32(&sw[buf][wr][4 * c]), wg + (size_t)kb * 224 + 4 * c);
        }
        cp_commit();
    };

    issue_tile(0, 0);
    for (int it = 0; it < 16; it++) {
        const int buf = it & 1;
        if (it + 1 < 16) { issue_tile(32 * (it + 1), buf ^ 1); cp_wait<1>(); }
        else             { cp_wait<0>(); }
        __syncthreads();
#pragma unroll 8
        for (int k = 0; k < 32; k++) {
            float xv = sx[buf][m][k];
            ull xp = pack2(xv, xv);
            const ulonglong2* wrow = (const ulonglong2*)&sw[buf][k][c0];
#pragma unroll
            for (int j = 0; j < 7; j++) {
                ulonglong2 w2 = wrow[j];
                fma2(acc[2 * j],     xp, w2.x);
                fma2(acc[2 * j + 1], xp, w2.y);
            }
        }
        __syncthreads();
    }

    float out[28];
#pragma unroll
    for (int j = 0; j < 14; j++) unpack2(acc[j], out[2 * j], out[2 * j + 1]);
    float* dst = &g_proj[(size_t)(mbase + m) * NREC];
    const float lb0 = lr_b[0];
    const int n0 = half * 112 + c0;
#pragma unroll
    for (int j = 0; j < 28; j++) {
        int n = n0 + j;
        if (n < 196) {
            float v = out[j] + g_bcat[n];
            if (n == 192) v = 1.f / (1.f + expf(-(out[j] + lb0)));
            dst[n] = v;
        }
    }
}

// ---------------------------------------------------------------------------
// Kernel 2: sequential TTT scan. ONE WARP per batch. Thread owns W rows
// o0=2*lane, o1=2*lane+1 (full 64 cols each) as f32x2 registers.
// No barriers; reductions are warp shfl butterflies. LN2 of token t-1 is
// pipelined behind token t's matvec. Distance-2/3 register prefetch of proj.
// ---------------------------------------------------------------------------
__global__ void __launch_bounds__(32) scan_kernel(
    const float* __restrict__ W0,
    const float* __restrict__ ln_g, const float* __restrict__ ln_b)
{
    __shared__ __align__(16) float sbuf[2][NREC];

    const int b    = blockIdx.x;
    const int lane = threadIdx.x;
    const int o0   = 2 * lane, o1 = o0 + 1;

    const float g0 = ln_g[o0], g1 = ln_g[o1];
    const float lb0 = ln_b[o0], lb1 = ln_b[o1];
    const float cc0 = g0 * g0, cc1 = g1 * g1;

    // Sc = sum_o g_o^2
    float Sc = cc0 + cc1;
#pragma unroll
    for (int off = 16; off; off >>= 1) Sc += __shfl_xor_sync(~0u, Sc, off);

    // W rows in registers (f32x2 pairs)
    ull w0[32], w1[32];
    {
        const float4* r0 = (const float4*)&W0[o0 * 64];
        const float4* r1 = (const float4*)&W0[o1 * 64];
#pragma unroll
        for (int j = 0; j < 16; j++) {
            float4 a = r0[j]; w0[2 * j] = pack2(a.x, a.y); w0[2 * j + 1] = pack2(a.z, a.w);
            float4 c = r1[j]; w1[2 * j] = pack2(c.x, c.y); w1[2 * j + 1] = pack2(c.z, c.w);
        }
    }

    const float4* p4 = (const float4*)(g_proj + (size_t)b * TT * NREC); // 64 f4/row
    float* hout = g_h + (size_t)b * TT * BD;

    // token 0 -> sbuf[0]; pS = token1 (store next iter), pL = token2 (in flight)
    *(float4*)&sbuf[0][4 * lane]        = p4[lane];
    *(float4*)&sbuf[0][4 * (lane + 32)] = p4[lane + 32];
    float4 pS0 = p4[64 + lane],  pS1 = p4[64 + lane + 32];
    float4 pL0 = p4[128 + lane], pL1 = p4[128 + lane + 32];
    __syncwarp();

    const float inv64 = 1.f / 64.f;
    const float twon  = 2.f / 64.f;
    const float mean_c = Sc * inv64;

    float pZqn0 = 0.f, pZqn1 = 0.f, pq0 = 0.f, pq1 = 0.f; // carried (token t-1)

    for (int t = 0; t < TT; t++) {
        const int cur = t & 1;
        const float* kb = &sbuf[cur][0];
        const float* vb = &sbuf[cur][64];
        const float* qb = &sbuf[cur][128];

        // order prev-iter smem reads before this iter's smem writes
        __syncwarp();

        // store token t+1 (loaded 2 iters ago); rotate; issue LDG token t+3
        *(float4*)&sbuf[cur ^ 1][4 * lane]        = pS0;
        *(float4*)&sbuf[cur ^ 1][4 * (lane + 32)] = pS1;
        pS0 = pL0; pS1 = pL1;
        if (t + 3 < TT) {
            size_t base = (size_t)(t + 3) * 64;
            pL0 = p4[base + lane];
            pL1 = p4[base + lane + 32];
        }

        // matvecs Z = W k, Zq = W q (k/q broadcast from smem)
        ull zk0a = 0, zk0b = 0, zk1a = 0, zk1b = 0;
        ull zq0a = 0, zq0b = 0, zq1a = 0, zq1b = 0;
#pragma unroll
        for (int j = 0; j < 32; j += 2) {
            ull kj0 = *(const ull*)&kb[2 * j];
            ull kj1 = *(const ull*)&kb[2 * j + 2];
            fma2(zk0a, w0[j], kj0);     fma2(zk1a, w1[j], kj0);
            fma2(zk0b, w0[j + 1], kj1); fma2(zk1b, w1[j + 1], kj1);
        }
#pragma unroll
        for (int j = 0; j < 32; j += 2) {
            ull qj0 = *(const ull*)&qb[2 * j];
            ull qj1 = *(const ull*)&qb[2 * j + 2];
            fma2(zq0a, w0[j], qj0);     fma2(zq1a, w1[j], qj0);
            fma2(zq0b, w0[j + 1], qj1); fma2(zq1b, w1[j + 1], qj1);
        }

        // LN2 of token t-1 (latency hides under the matvec FMA issue above)
        if (t > 0) {
            float s0 = pZqn0 + pZqn1;
            float s1 = pZqn0 * pZqn0 + pZqn1 * pZqn1;
#pragma unroll
            for (int off = 16; off; off >>= 1) {
                s0 += __shfl_xor_sync(~0u, s0, off);
                s1 += __shfl_xor_sync(~0u, s1, off);
            }
            float mu2 = s0 * inv64;
            float rs2 = rsqrtf(s1 * inv64 - mu2 * mu2 + 1e-6f);
            float h0 = pq0 + (pZqn0 - mu2) * rs2 * g0 + lb0;
            float h1 = pq1 + (pZqn1 - mu2) * rs2 * g1 + lb1;
            *(ull*)&hout[(size_t)(t - 1) * BD + o0] = pack2(h0, h1);
        }

        float ta, tb, tc, td;
        unpack2(zk0a, ta, tb); unpack2(zk0b, tc, td); float Z0  = (ta + tb) + (tc + td);
        unpack2(zk1a, ta, tb); unpack2(zk1b, tc, td); float Z1  = (ta + tb) + (tc + td);
        unpack2(zq0a, ta, tb); unpack2(zq0b, tc, td); float Zq0 = (ta + tb) + (tc + td);
        unpack2(zq1a, ta, tb); unpack2(zq1b, tc, td); float Zq1 = (ta + tb) + (tc + td);

        // this thread's own k,v,q entries (pair loads, conflict-free)
        float k0p, k1p, v0p, v1p, q0p, q1p;
        unpack2(*(const ull*)&kb[o0], k0p, k1p);
        unpack2(*(const ull*)&vb[o0], v0p, v1p);
        unpack2(*(const ull*)&qb[o0], q0p, q1p);
        const float eta = kb[192];

        const float a0 = g0 * (k0p - v0p + lb0);
        const float a1 = g1 * (k1p - v1p + lb1);

        // merged reduction: {Z, Z^2, aZ, cZ, cZ^2, a, k.q}
        float r0 = Z0 + Z1;
        float r1 = Z0 * Z0 + Z1 * Z1;
        float r2 = a0 * Z0 + a1 * Z1;
        float r3 = cc0 * Z0 + cc1 * Z1;
        float r4 = cc0 * Z0 * Z0 + cc1 * Z1 * Z1;
        float r5 = a0 + a1;
        float r6 = k0p * q0p + k1p * q1p;
#pragma unroll
        for (int off = 16; off; off >>= 1) {
            r0 += __shfl_xor_sync(~0u, r0, off);
            r1 += __shfl_xor_sync(~0u, r1, off);
            r2 += __shfl_xor_sync(~0u, r2, off);
            r3 += __shfl_xor_sync(~0u, r3, off);
            r4 += __shfl_xor_sync(~0u, r4, off);
            r5 += __shfl_xor_sync(~0u, r5, off);
            r6 += __shfl_xor_sync(~0u, r6, off);
        }
        const float mu  = r0 * inv64;
        const float var = r1 * inv64 - mu * mu;
        const float rs  = rsqrtf(var + 1e-6f);
        const float mean_aZ  = r2 * inv64;
        const float mean_cZ  = r3 * inv64;
        const float mean_cZ2 = r4 * inv64;
        const float mean_a   = r5 * inv64;
        const float kq       = r6;

        const float m1 = twon * (mean_a + rs * (mean_cZ - mu * mean_c));
        const float m2 = twon * (rs * (mean_aZ - mu * mean_a)
                        + rs * rs * (mean_cZ2 - 2.f * mu * mean_cZ + mu * mu * mean_c));
        const float zh0 = (Z0 - mu) * rs, zh1 = (Z1 - mu) * rs;
        const float gz0 = rs * (twon * (a0 + cc0 * zh0) - m1 - zh0 * m2);
        const float gz1 = rs * (twon * (a1 + cc1 * zh1) - m1 - zh1 * m2);
        const float coef0 = eta * gz0, coef1 = eta * gz1;

        // rank-1 update: W[o][:] -= coef_o * k
        const ull nc0 = pack2(-coef0, -coef0);
        const ull nc1 = pack2(-coef1, -coef1);
#pragma unroll
        for (int j = 0; j < 32; j++) {
            ull kj = *(const ull*)&kb[2 * j];
            fma2(w0[j], nc0, kj);
            fma2(w1[j], nc1, kj);
        }

        // q matvec on W_new via rank-1 correction
        pZqn0 = Zq0 - coef0 * kq;
        pZqn1 = Zq1 - coef1 * kq;
        pq0 = q0p; pq1 = q1p;
    }

    // LN2 + store for final token
    {
        float s0 = pZqn0 + pZqn1;
        float s1 = pZqn0 * pZqn0 + pZqn1 * pZqn1;
#pragma unroll
        for (int off = 16; off; off >>= 1) {
            s0 += __shfl_xor_sync(~0u, s0, off);
            s1 += __shfl_xor_sync(~0u, s1, off);
        }
        float mu2 = s0 * inv64;
        float rs2 = rsqrtf(s1 * inv64 - mu2 * mu2 + 1e-6f);
        float h0 = pq0 + (pZqn0 - mu2) * rs2 * g0 + lb0;
        float h1 = pq1 + (pZqn1 - mu2) * rs2 * g1 + lb1;
        *(ull*)&hout[(size_t)(TT - 1) * BD + o0] = pack2(h0, h1);
    }
}

// ---------------------------------------------------------------------------
// Kernel 3: z = h @ Wo + bo.  M=32768, K=64, N=512. BM=64, BN=64.
// ---------------------------------------------------------------------------
__global__ void __launch_bounds__(256) out_kernel(
    const float* __restrict__ Wo, const float* __restrict__ bo,
    float* __restrict__ z)
{
    __shared__ float sh[64][65];
    __shared__ float sw2[64][64];

    const int tid = threadIdx.x;
    const int mbase = blockIdx.x * 64;
    const int nbase = blockIdx.y * 64;
    const int m  = tid >> 2;
    const int ng = tid & 3;

    for (int i = tid; i < 1024; i += 256) {
        int row = i >> 4;
        int c = (i & 15) * 4;
        float4 v = *(const float4*)&g_h[(size_t)(mbase + row) * BD + c];
        sh[row][c] = v.x; sh[row][c + 1] = v.y; sh[row][c + 2] = v.z; sh[row][c + 3] = v.w;
        *(float4*)&sw2[row][c] = *(const float4*)&Wo[(size_t)row * DD + nbase + c];
    }
    __syncthreads();

    ull acc[8];
#pragma unroll
    for (int j = 0; j < 8; j++) acc[j] = 0ull;
#pragma unroll 8
    for (int k = 0; k < 64; k++) {
        float hv = sh[m][k];
        ull hp = pack2(hv, hv);
#pragma unroll
        for (int j = 0; j < 4; j++) {
            // cols ng*4 + 16*j .. +3 : conflict-free LDS.128 across ng
            ulonglong2 w2 = *(const ulonglong2*)&sw2[k][ng * 4 + 16 * j];
            fma2(acc[2 * j],     hp, w2.x);
            fma2(acc[2 * j + 1], hp, w2.y);
        }
    }
    float out[16];
#pragma unroll
    for (int j = 0; j < 8; j++) unpack2(acc[j], out[2 * j], out[2 * j + 1]);
    float* dstrow = &z[(size_t)(mbase + m) * DD];
#pragma unroll
    for (int j = 0; j < 4; j++) {
        int c = nbase + ng * 4 + 16 * j;
        float4 bv = *(const float4*)&bo[c];
        float4 o4 = make_float4(out[4 * j] + bv.x, out[4 * j + 1] + bv.y,
                                out[4 * j + 2] + bv.z, out[4 * j + 3] + bv.w);
        *(float4*)&dstrow[c] = o4;
    }
}

// ---------------------------------------------------------------------------
extern "C" void kernel_launch(void* const* d_in, const int* in_sizes, int n_in,
                              void* d_out, int out_size)
{
    const float* x    = (const float*)d_in[0];
    const float* Wk   = (const float*)d_in[1];
    const float* bk   = (const float*)d_in[2];
    const float* Wv   = (const float*)d_in[3];
    const float* bv   = (const float*)d_in[4];
    const float* Wq   = (const float*)d_in[5];
    const float* bq   = (const float*)d_in[6];
    const float* Wo   = (const float*)d_in[7];
    const float* bo   = (const float*)d_in[8];
    const float* ln_g = (const float*)d_in[9];
    const float* ln_b = (const float*)d_in[10];
    const float* lr_w = (const float*)d_in[11];
    const float* lr_b = (const float*)d_in[12];
    const float* W0   = (const float*)d_in[13];
    float* z = (float*)d_out;

    prep_kernel<<<448, 256>>>(Wk, Wv, Wq, lr_w, bk, bv, bq);
    proj_kernel<<<dim3(512, 2), 256>>>(x, lr_b);
    scan_kernel<<<BB, 32>>>(W0, ln_g, ln_b);
    out_kernel<<<dim3(512, 8), 256>>>(Wo, bo, z);
}

// round 4
// speedup vs baseline: 1.8214x; 1.2658x over previous
#include <cuda_runtime.h>

#define BB 16
#define TT 2048
#define DD 512
#define BD 64
#define NREC 256   // padded row: k(64) v(64) q(64) eta@192, pad to 256

__device__ float g_proj[(size_t)BB * TT * NREC];   // 33.5 MB
__device__ float g_h[(size_t)BB * TT * BD];        // 8.4 MB
__device__ float g_wcat[512 * 224];
__device__ float g_bcat[224];

typedef unsigned long long ull;

__device__ __forceinline__ ull pack2(float a, float b) {
    ull r; asm("mov.b64 %0, {%1, %2};" : "=l"(r) : "f"(a), "f"(b)); return r;
}
__device__ __forceinline__ void unpack2(ull v, float& a, float& b) {
    asm("mov.b64 {%0, %1}, %2;" : "=f"(a), "=f"(b) : "l"(v));
}
__device__ __forceinline__ void fma2(ull& d, ull a, ull b) {
    asm("fma.rn.f32x2 %0, %1, %2, %0;" : "+l"(d) : "l"(a), "l"(b));
}
__device__ __forceinline__ unsigned smem_u32(const void* p) {
    return (unsigned)__cvta_generic_to_shared(p);
}
__device__ __forceinline__ void cp16(unsigned dst, const void* src) {
    asm volatile("cp.async.cg.shared.global [%0], [%1], 16;" :: "r"(dst), "l"(src));
}
__device__ __forceinline__ void cp_commit() { asm volatile("cp.async.commit_group;"); }
template<int N> __device__ __forceinline__ void cp_wait() {
    asm volatile("cp.async.wait_group %0;" :: "n"(N));
}

// ---------------------------------------------------------------------------
// Kernel 0: pack Wcat[512][224] = [Wk|Wv|Wq|lr_w|pad], bcat[224]
// ---------------------------------------------------------------------------
__global__ void prep_kernel(
    const float* __restrict__ Wk, const float* __restrict__ Wv,
    const float* __restrict__ Wq, const float* __restrict__ lr_w,
    const float* __restrict__ bk, const float* __restrict__ bv,
    const float* __restrict__ bq)
{
    int idx = blockIdx.x * 256 + threadIdx.x;
    if (idx >= 512 * 224) return;
    int r = idx / 224, n = idx % 224;
    float v = 0.f;
    if      (n < 64)   v = Wk[r * 64 + n];
    else if (n < 128)  v = Wv[r * 64 + n - 64];
    else if (n < 192)  v = Wq[r * 64 + n - 128];
    else if (n == 192) v = lr_w[r];
    g_wcat[idx] = v;
    if (r == 0) {
        float bvv = 0.f;
        if      (n < 64)  bvv = bk[n];
        else if (n < 128) bvv = bv[n - 64];
        else if (n < 192) bvv = bq[n - 128];
        g_bcat[n] = bvv;
    }
}

// ---------------------------------------------------------------------------
// Kernel 1: proj = x @ Wcat.  M=32768, K=512, BM=128 (2 rows/thread), KT=16,
// Ntile=112 (grid.y=2). cp.async double-buffered.
// ---------------------------------------------------------------------------
__global__ void __launch_bounds__(256) proj_kernel(
    const float* __restrict__ x, const float* __restrict__ lr_b)
{
    __shared__ float sx[2][128][20];   // [buf][m][k], pad 16->20  (20480 B)
    __shared__ float sw[2][16][112];   // [buf][k][n]              (14336 B)

    const int tid   = threadIdx.x;
    const int mbase = blockIdx.x * 128;
    const int half  = blockIdx.y;
    const int m  = tid >> 2;           // 0..63 -> rows m, m+64
    const int ng = tid & 3;
    const int c0 = ng * 28;

    // cp.async mapping
    const int xr = tid >> 1, xq = tid & 1;     // x: 128 rows, f4-cols {xq, xq+2}
    const float* xg = x + (size_t)(mbase + xr) * DD;
    // w: 448 f4 -> thread covers tid and tid+256 (if < 448)
    const int wr0 = tid / 28, wc0 = tid % 28;
    const int wi1 = tid + 256;
    const int wr1 = wi1 / 28, wc1 = wi1 % 28;
    const float* wg = g_wcat + half * 112;

    ull acc0[14], acc1[14];
#pragma unroll
    for (int j = 0; j < 14; j++) { acc0[j] = 0ull; acc1[j] = 0ull; }

    auto issue_tile = [&](int kb, int buf) {
        cp16(smem_u32(&sx[buf][xr][4 * xq]),       xg + kb + 4 * xq);
        cp16(smem_u32(&sx[buf][xr][4 * (xq + 2)]), xg + kb + 4 * (xq + 2));
        cp16(smem_u32(&sw[buf][wr0][4 * wc0]), wg + (size_t)(kb + wr0) * 224 + 4 * wc0);
        if (wi1 < 448)
            cp16(smem_u32(&sw[buf][wr1][4 * wc1]), wg + (size_t)(kb + wr1) * 224 + 4 * wc1);
        cp_commit();
    };

    issue_tile(0, 0);
    for (int it = 0; it < 32; it++) {
        const int buf = it & 1;
        if (it + 1 < 32) { issue_tile(16 * (it + 1), buf ^ 1); cp_wait<1>(); }
        else             { cp_wait<0>(); }
        __syncthreads();
#pragma unroll
        for (int k = 0; k < 16; k++) {
            float xa = sx[buf][m][k];
            float xb = sx[buf][m + 64][k];
            ull xpa = pack2(xa, xa);
            ull xpb = pack2(xb, xb);
            const ulonglong2* wrow = (const ulonglong2*)&sw[buf][k][c0];
#pragma unroll
            for (int j = 0; j < 7; j++) {
                ulonglong2 w2 = wrow[j];
                fma2(acc0[2 * j],     xpa, w2.x);
                fma2(acc0[2 * j + 1], xpa, w2.y);
                fma2(acc1[2 * j],     xpb, w2.x);
                fma2(acc1[2 * j + 1], xpb, w2.y);
            }
        }
        __syncthreads();
    }

    const float lb0 = lr_b[0];
    const int n0 = half * 112 + c0;
#pragma unroll
    for (int rsel = 0; rsel < 2; rsel++) {
        float out[28];
        ull* acc = rsel ? acc1 : acc0;
#pragma unroll
        for (int j = 0; j < 14; j++) unpack2(acc[j], out[2 * j], out[2 * j + 1]);
        float* dst = &g_proj[(size_t)(mbase + m + 64 * rsel) * NREC];
#pragma unroll
        for (int j = 0; j < 28; j++) {
            int n = n0 + j;
            if (n < 196) {
                float v = out[j] + g_bcat[n];
                if (n == 192) v = 1.f / (1.f + expf(-(out[j] + lb0)));
                dst[n] = v;
            }
        }
    }
}

// ---------------------------------------------------------------------------
// Kernel 2: sequential TTT scan, ONE WARP per batch, LAGGED-W pipeline.
// Invariant entering iter t:  Wreg = W_{t-2};  M/Mq = W_{t-2}·{k_t,q_t};
// Gkk = k_{t-1}·k_t; Gkq = k_{t-1}·q_t; cg = eta_{t-1}·gz_{t-1}[own rows].
// Z_t = M - cg*Gkk (2 FMAs).  One 11-value butterfly per token (LN1 stats,
// Grams for t+1, LN2 stats of t-1).  W update (token t-1) + lagged matvecs
// for t+1 are dependency-free bulk FMA work issued under the butterfly.
// ---------------------------------------------------------------------------
__global__ void __launch_bounds__(32) scan_kernel(
    const float* __restrict__ W0,
    const float* __restrict__ ln_g, const float* __restrict__ ln_b)
{
    __shared__ __align__(16) float sbuf[4][NREC];   // 4-deep token ring

    const int b    = blockIdx.x;
    const int lane = threadIdx.x;
    const int o0   = 2 * lane, o1 = o0 + 1;

    const float g0 = ln_g[o0], g1 = ln_g[o1];
    const float lb0 = ln_b[o0], lb1 = ln_b[o1];
    const float cc0 = g0 * g0, cc1 = g1 * g1;

    float Sc = cc0 + cc1;
#pragma unroll
    for (int off = 16; off; off >>= 1) Sc += __shfl_xor_sync(~0u, Sc, off);

    ull w0[32], w1[32];
    {
        const float4* r0 = (const float4*)&W0[o0 * 64];
        const float4* r1 = (const float4*)&W0[o1 * 64];
#pragma unroll
        for (int j = 0; j < 16; j++) {
            float4 a = r0[j]; w0[2 * j] = pack2(a.x, a.y); w0[2 * j + 1] = pack2(a.z, a.w);
            float4 c = r1[j]; w1[2 * j] = pack2(c.x, c.y); w1[2 * j + 1] = pack2(c.z, c.w);
        }
    }

    const float4* p4 = (const float4*)(g_proj + (size_t)b * TT * NREC); // 64 f4/token
    float* hout = g_h + (size_t)b * TT * BD;

    // dot of both owned W rows with a 64-float vector in smem
    auto mv = [&](const float* vsrc, float& d0, float& d1) {
        ull A0 = 0, A1 = 0, B0 = 0, B1 = 0;
#pragma unroll
        for (int j = 0; j < 16; j++) {
            ulonglong2 vv = *(const ulonglong2*)&vsrc[4 * j];
            fma2(A0, w0[2 * j], vv.x); fma2(A1, w0[2 * j + 1], vv.y);
            fma2(B0, w1[2 * j], vv.x); fma2(B1, w1[2 * j + 1], vv.y);
        }
        float p, q, r, s;
        unpack2(A0, p, q); unpack2(A1, r, s); d0 = (p + q) + (r + s);
        unpack2(B0, p, q); unpack2(B1, r, s); d1 = (p + q) + (r + s);
    };
    // rank-1: W[own rows] -= cg * kvec
    auto upd = [&](const float* ksrc, float c0u, float c1u) {
        ull n0 = pack2(-c0u, -c0u), n1 = pack2(-c1u, -c1u);
#pragma unroll
        for (int j = 0; j < 16; j++) {
            ulonglong2 kk = *(const ulonglong2*)&ksrc[4 * j];
            fma2(w0[2 * j], n0, kk.x); fma2(w0[2 * j + 1], n0, kk.y);
            fma2(w1[2 * j], n1, kk.x); fma2(w1[2 * j + 1], n1, kk.y);
        }
    };

    // prologue: zero ring slot 3 (read as "token -1"); tokens 0,1 -> slots 0,1
    float4 z4 = make_float4(0.f, 0.f, 0.f, 0.f);
    *(float4*)&sbuf[3][4 * lane] = z4; *(float4*)&sbuf[3][4 * (lane + 32)] = z4;
    *(float4*)&sbuf[0][4 * lane] = p4[lane];
    *(float4*)&sbuf[0][4 * (lane + 32)] = p4[lane + 32];
    *(float4*)&sbuf[1][4 * lane] = p4[64 + lane];
    *(float4*)&sbuf[1][4 * (lane + 32)] = p4[64 + lane + 32];
    float4 pS0 = p4[128 + lane], pS1 = p4[128 + lane + 32];   // token 2
    float4 pL0 = p4[192 + lane], pL1 = p4[192 + lane + 32];   // token 3
    __syncwarp();

    float M0, M1, Mq0, Mq1;
    mv(&sbuf[0][0],   M0,  M1);     // W0·k_0
    mv(&sbuf[0][128], Mq0, Mq1);    // W0·q_0

    const float inv64 = 1.f / 64.f;
    const float twon  = 2.f / 64.f;
    const float mean_c = Sc * inv64;

    float cg0 = 0.f, cg1 = 0.f, Gkk = 0.f, Gkq = 0.f;
    float pZqn0 = 0.f, pZqn1 = 0.f, pq0 = 0.f, pq1 = 0.f;

    for (int t = 0; t < TT; t++) {
        const int cur = t & 3, nxt = (t + 1) & 3, prv = (t - 1) & 3, st2 = (t + 2) & 3;
        const float* kb = &sbuf[cur][0];

        __syncwarp();
        // store token t+2 (in pS), rotate, issue LDG token t+4
        if (t + 2 < TT) {
            *(float4*)&sbuf[st2][4 * lane]        = pS0;
            *(float4*)&sbuf[st2][4 * (lane + 32)] = pS1;
        }
        pS0 = pL0; pS1 = pL1;
        if (t + 4 < TT) {
            size_t base = (size_t)(t + 4) * 64;
            pL0 = p4[base + lane]; pL1 = p4[base + lane + 32];
        }

        // Z via rank-1 correction (W_{t-1}·k_t from lagged matvec)
        const float Z0 = M0 - cg0 * Gkk;
        const float Z1 = M1 - cg1 * Gkk;

        // own entries of token t and token t+1
        float k0p, k1p, v0p, v1p, q0p, q1p, kn0, kn1, qn0, qn1;
        unpack2(*(const ull*)&kb[o0],        k0p, k1p);
        unpack2(*(const ull*)&kb[64 + o0],   v0p, v1p);
        unpack2(*(const ull*)&kb[128 + o0],  q0p, q1p);
        unpack2(*(const ull*)&sbuf[nxt][o0],       kn0, kn1);
        unpack2(*(const ull*)&sbuf[nxt][128 + o0], qn0, qn1);
        const float eta = kb[192];

        const float a0 = g0 * (k0p - v0p + lb0);
        const float a1 = g1 * (k1p - v1p + lb1);

        // bulk FMA work, independent of this token's butterfly:
        // apply token t-1's rank-1 update, then lagged matvecs for token t+1
        upd(&sbuf[prv][0], cg0, cg1);               // Wreg: W_{t-2} -> W_{t-1}
        float Mn0, Mn1, Mqn0, Mqn1;
        mv(&sbuf[nxt][0],   Mn0,  Mn1);             // W_{t-1}·k_{t+1}
        mv(&sbuf[nxt][128], Mqn0, Mqn1);            // W_{t-1}·q_{t+1}

        // 11-value butterfly
        float r0 = Z0 + Z1;
        float r1 = Z0 * Z0 + Z1 * Z1;
        float r2 = a0 * Z0 + a1 * Z1;
        float r3 = cc0 * Z0 + cc1 * Z1;
        float r4 = cc0 * Z0 * Z0 + cc1 * Z1 * Z1;
        float r5 = a0 + a1;
        float r6 = k0p * q0p + k1p * q1p;           // k_t·q_t
        float r7 = k0p * kn0 + k1p * kn1;           // k_t·k_{t+1}
        float r8 = k0p * qn0 + k1p * qn1;           // k_t·q_{t+1}
        float r9  = pZqn0 + pZqn1;                  // LN2 stats (token t-1)
        float r10 = pZqn0 * pZqn0 + pZqn1 * pZqn1;
#pragma unroll
        for (int off = 16; off; off >>= 1) {
            r0 += __shfl_xor_sync(~0u, r0, off);
            r1 += __shfl_xor_sync(~0u, r1, off);
            r2 += __shfl_xor_sync(~0u, r2, off);
            r3 += __shfl_xor_sync(~0u, r3, off);
            r4 += __shfl_xor_sync(~0u, r4, off);
            r5 += __shfl_xor_sync(~0u, r5, off);
            r6 += __shfl_xor_sync(~0u, r6, off);
            r7 += __shfl_xor_sync(~0u, r7, off);
            r8 += __shfl_xor_sync(~0u, r8, off);
            r9 += __shfl_xor_sync(~0u, r9, off);
            r10 += __shfl_xor_sync(~0u, r10, off);
        }

        const float mu  = r0 * inv64;
        const float var = r1 * inv64 - mu * mu;
        const float rs  = rsqrtf(var + 1e-6f);
        const float mean_aZ  = r2 * inv64;
        const float mean_cZ  = r3 * inv64;
        const float mean_cZ2 = r4 * inv64;
        const float mean_a   = r5 * inv64;
        const float kq       = r6;

        const float m1 = twon * (mean_a + rs * (mean_cZ - mu * mean_c));
        const float m2 = twon * (rs * (mean_aZ - mu * mean_a)
                        + rs * rs * (mean_cZ2 - 2.f * mu * mean_cZ + mu * mu * mean_c));
        const float zh0 = (Z0 - mu) * rs, zh1 = (Z1 - mu) * rs;
        const float gz0 = rs * (twon * (a0 + cc0 * zh0) - m1 - zh0 * m2);
        const float gz1 = rs * (twon * (a1 + cc1 * zh1) - m1 - zh1 * m2);
        const float coef0 = eta * gz0, coef1 = eta * gz1;

        // LN2 + store h for token t-1
        if (t > 0) {
            const float mu2 = r9 * inv64;
            const float rs2 = rsqrtf(r10 * inv64 - mu2 * mu2 + 1e-6f);
            const float h0 = pq0 + (pZqn0 - mu2) * rs2 * g0 + lb0;
            const float h1 = pq1 + (pZqn1 - mu2) * rs2 * g1 + lb1;
            *(ull*)&hout[(size_t)(t - 1) * BD + o0] = pack2(h0, h1);
        }

        // Zq_t on W_t via two corrections
        pZqn0 = (Mq0 - cg0 * Gkq) - coef0 * kq;
        pZqn1 = (Mq1 - cg1 * Gkq) - coef1 * kq;
        pq0 = q0p; pq1 = q1p;

        // carry state for iter t+1
        cg0 = coef0; cg1 = coef1;
        Gkk = r7; Gkq = r8;
        M0 = Mn0; M1 = Mn1; Mq0 = Mqn0; Mq1 = Mqn1;
    }

    // LN2 + store for final token
    {
        float s0 = pZqn0 + pZqn1;
        float s1 = pZqn0 * pZqn0 + pZqn1 * pZqn1;
#pragma unroll
        for (int off = 16; off; off >>= 1) {
            s0 += __shfl_xor_sync(~0u, s0, off);
            s1 += __shfl_xor_sync(~0u, s1, off);
        }
        float mu2 = s0 * inv64;
        float rs2 = rsqrtf(s1 * inv64 - mu2 * mu2 + 1e-6f);
        float h0 = pq0 + (pZqn0 - mu2) * rs2 * g0 + lb0;
        float h1 = pq1 + (pZqn1 - mu2) * rs2 * g1 + lb1;
        *(ull*)&hout[(size_t)(TT - 1) * BD + o0] = pack2(h0, h1);
    }
}

// ---------------------------------------------------------------------------
// Kernel 3: z = h @ Wo + bo.  M=32768, K=64, N=512. BM=64 (2 rows/thread),
// BN=64, 128 threads.
// ---------------------------------------------------------------------------
__global__ void __launch_bounds__(128) out_kernel(
    const float* __restrict__ Wo, const float* __restrict__ bo,
    float* __restrict__ z)
{
    __shared__ float sh[64][68];    // pad 64->68 (f4-aligned, conflict-free)
    __shared__ float sw2[64][64];

    const int tid = threadIdx.x;
    const int mbase = blockIdx.x * 64;
    const int nbase = blockIdx.y * 64;
    const int m  = tid >> 2;        // 0..31 -> rows m, m+32
    const int ng = tid & 3;

    for (int i = tid; i < 1024; i += 128) {
        int row = i >> 4;
        int c = (i & 15) * 4;
        *(float4*)&sh[row][c]  = *(const float4*)&g_h[(size_t)(mbase + row) * BD + c];
        *(float4*)&sw2[row][c] = *(const float4*)&Wo[(size_t)row * DD + nbase + c];
    }
    __syncthreads();

    ull acc0[8], acc1[8];
#pragma unroll
    for (int j = 0; j < 8; j++) { acc0[j] = 0ull; acc1[j] = 0ull; }
#pragma unroll 8
    for (int k = 0; k < 64; k++) {
        float ha = sh[m][k];
        float hb = sh[m + 32][k];
        ull hpa = pack2(ha, ha);
        ull hpb = pack2(hb, hb);
#pragma unroll
        for (int j = 0; j < 4; j++) {
            ulonglong2 w2 = *(const ulonglong2*)&sw2[k][ng * 4 + 16 * j];
            fma2(acc0[2 * j],     hpa, w2.x);
            fma2(acc0[2 * j + 1], hpa, w2.y);
            fma2(acc1[2 * j],     hpb, w2.x);
            fma2(acc1[2 * j + 1], hpb, w2.y);
        }
    }
#pragma unroll
    for (int rsel = 0; rsel < 2; rsel++) {
        ull* acc = rsel ? acc1 : acc0;
        float out[16];
#pragma unroll
        for (int j = 0; j < 8; j++) unpack2(acc[j], out[2 * j], out[2 * j + 1]);
        float* dstrow = &z[(size_t)(mbase + m + 32 * rsel) * DD];
#pragma unroll
        for (int j = 0; j < 4; j++) {
            int c = nbase + ng * 4 + 16 * j;
            float4 bv = *(const float4*)&bo[c];
            *(float4*)&dstrow[c] = make_float4(out[4 * j] + bv.x, out[4 * j + 1] + bv.y,
                                               out[4 * j + 2] + bv.z, out[4 * j + 3] + bv.w);
        }
    }
}

// ---------------------------------------------------------------------------
extern "C" void kernel_launch(void* const* d_in, const int* in_sizes, int n_in,
                              void* d_out, int out_size)
{
    const float* x    = (const float*)d_in[0];
    const float* Wk   = (const float*)d_in[1];
    const float* bk   = (const float*)d_in[2];
    const float* Wv   = (const float*)d_in[3];
    const float* bv   = (const float*)d_in[4];
    const float* Wq   = (const float*)d_in[5];
    const float* bq   = (const float*)d_in[6];
    const float* Wo   = (const float*)d_in[7];
    const float* bo   = (const float*)d_in[8];
    const float* ln_g = (const float*)d_in[9];
    const float* ln_b = (const float*)d_in[10];
    const float* lr_w = (const float*)d_in[11];
    const float* lr_b = (const float*)d_in[12];
    const float* W0   = (const float*)d_in[13];
    float* z = (float*)d_out;

    prep_kernel<<<448, 256>>>(Wk, Wv, Wq, lr_w, bk, bv, bq);
    proj_kernel<<<dim3(256, 2), 256>>>(x, lr_b);
    scan_kernel<<<BB, 32>>>(W0, ln_g, ln_b);
    out_kernel<<<dim3(512, 8), 128>>>(Wo, bo, z);
}

// round 5
// speedup vs baseline: 1.8982x; 1.0422x over previous
#include <cuda_runtime.h>

#define BB 16
#define TT 2048
#define DD 512
#define BD 64
#define NREC 256   // padded row: k(64) v(64) q(64) eta@192, pad to 256

__device__ float g_proj[(size_t)BB * TT * NREC];   // 33.5 MB
__device__ float g_h[(size_t)BB * TT * BD];        // 8.4 MB
__device__ float g_wcat[512 * 224];
__device__ float g_bcat[224];

typedef unsigned long long ull;

__device__ __forceinline__ ull pack2(float a, float b) {
    ull r; asm("mov.b64 %0, {%1, %2};" : "=l"(r) : "f"(a), "f"(b)); return r;
}
__device__ __forceinline__ void unpack2(ull v, float& a, float& b) {
    asm("mov.b64 {%0, %1}, %2;" : "=f"(a), "=f"(b) : "l"(v));
}
__device__ __forceinline__ void fma2(ull& d, ull a, ull b) {
    asm("fma.rn.f32x2 %0, %1, %2, %0;" : "+l"(d) : "l"(a), "l"(b));
}
__device__ __forceinline__ unsigned smem_u32(const void* p) {
    return (unsigned)__cvta_generic_to_shared(p);
}
__device__ __forceinline__ void cp16(unsigned dst, const void* src) {
    asm volatile("cp.async.cg.shared.global [%0], [%1], 16;" :: "r"(dst), "l"(src));
}
__device__ __forceinline__ void cp_commit() { asm volatile("cp.async.commit_group;"); }
template<int N> __device__ __forceinline__ void cp_wait() {
    asm volatile("cp.async.wait_group %0;" :: "n"(N));
}

// ---------------------------------------------------------------------------
// Kernel 0: pack Wcat[512][224] = [Wk|Wv|Wq|lr_w|pad], bcat[224]
// ---------------------------------------------------------------------------
__global__ void prep_kernel(
    const float* __restrict__ Wk, const float* __restrict__ Wv,
    const float* __restrict__ Wq, const float* __restrict__ lr_w,
    const float* __restrict__ bk, const float* __restrict__ bv,
    const float* __restrict__ bq)
{
    int idx = blockIdx.x * 256 + threadIdx.x;
    if (idx >= 512 * 224) return;
    int r = idx / 224, n = idx % 224;
    float v = 0.f;
    if      (n < 64)   v = Wk[r * 64 + n];
    else if (n < 128)  v = Wv[r * 64 + n - 64];
    else if (n < 192)  v = Wq[r * 64 + n - 128];
    else if (n == 192) v = lr_w[r];
    g_wcat[idx] = v;
    if (r == 0) {
        float bvv = 0.f;
        if      (n < 64)  bvv = bk[n];
        else if (n < 128) bvv = bv[n - 64];
        else if (n < 192) bvv = bq[n - 128];
        g_bcat[n] = bvv;
    }
}

// ---------------------------------------------------------------------------
// Kernel 1: proj = x @ Wcat.  M=32768, K=512, BM=128 (2 rows/thread), KT=16,
// Ntile=112 (grid.y=2). cp.async double-buffered.
// ---------------------------------------------------------------------------
__global__ void __launch_bounds__(256) proj_kernel(
    const float* __restrict__ x, const float* __restrict__ lr_b)
{
    __shared__ float sx[2][128][20];   // [buf][m][k], pad 16->20
    __shared__ float sw[2][16][112];   // [buf][k][n]

    const int tid   = threadIdx.x;
    const int mbase = blockIdx.x * 128;
    const int half  = blockIdx.y;
    const int m  = tid >> 2;           // 0..63 -> rows m, m+64
    const int ng = tid & 3;
    const int c0 = ng * 28;

    const int xr = tid >> 1, xq = tid & 1;
    const float* xg = x + (size_t)(mbase + xr) * DD;
    const int wr0 = tid / 28, wc0 = tid % 28;
    const int wi1 = tid + 256;
    const int wr1 = wi1 / 28, wc1 = wi1 % 28;
    const float* wg = g_wcat + half * 112;

    ull acc0[14], acc1[14];
#pragma unroll
    for (int j = 0; j < 14; j++) { acc0[j] = 0ull; acc1[j] = 0ull; }

    auto issue_tile = [&](int kb, int buf) {
        cp16(smem_u32(&sx[buf][xr][4 * xq]),       xg + kb + 4 * xq);
        cp16(smem_u32(&sx[buf][xr][4 * (xq + 2)]), xg + kb + 4 * (xq + 2));
        cp16(smem_u32(&sw[buf][wr0][4 * wc0]), wg + (size_t)(kb + wr0) * 224 + 4 * wc0);
        if (wi1 < 448)
            cp16(smem_u32(&sw[buf][wr1][4 * wc1]), wg + (size_t)(kb + wr1) * 224 + 4 * wc1);
        cp_commit();
    };

    issue_tile(0, 0);
    for (int it = 0; it < 32; it++) {
        const int buf = it & 1;
        if (it + 1 < 32) { issue_tile(16 * (it + 1), buf ^ 1); cp_wait<1>(); }
        else             { cp_wait<0>(); }
        __syncthreads();
#pragma unroll
        for (int k = 0; k < 16; k++) {
            float xa = sx[buf][m][k];
            float xb = sx[buf][m + 64][k];
            ull xpa = pack2(xa, xa);
            ull xpb = pack2(xb, xb);
            const ulonglong2* wrow = (const ulonglong2*)&sw[buf][k][c0];
#pragma unroll
            for (int j = 0; j < 7; j++) {
                ulonglong2 w2 = wrow[j];
                fma2(acc0[2 * j],     xpa, w2.x);
                fma2(acc0[2 * j + 1], xpa, w2.y);
                fma2(acc1[2 * j],     xpb, w2.x);
                fma2(acc1[2 * j + 1], xpb, w2.y);
            }
        }
        __syncthreads();
    }

    const float lb0 = lr_b[0];
    const int n0 = half * 112 + c0;
#pragma unroll
    for (int rsel = 0; rsel < 2; rsel++) {
        float out[28];
        ull* acc = rsel ? acc1 : acc0;
#pragma unroll
        for (int j = 0; j < 14; j++) unpack2(acc[j], out[2 * j], out[2 * j + 1]);
        float* dst = &g_proj[(size_t)(mbase + m + 64 * rsel) * NREC];
#pragma unroll
        for (int j = 0; j < 28; j++) {
            int n = n0 + j;
            if (n < 196) {
                float v = out[j] + g_bcat[n];
                if (n == 192) v = 1.f / (1.f + expf(-(out[j] + lb0)));
                dst[n] = v;
            }
        }
    }
}

// ---------------------------------------------------------------------------
// Kernel 2: sequential TTT scan, TWO WARPS per batch (column split), lagged-W.
// Lane owns rows o0=2*lane, o1=o0+1; warp w owns columns [32w, 32w+32).
// Per token: halved upd + lagged matvec partials, one STS.128 + bar + LDS.128
// exchange of partial dots, duplicated 11-value butterfly + scalars.
// ---------------------------------------------------------------------------
__global__ void __launch_bounds__(64) scan_kernel(
    const float* __restrict__ W0,
    const float* __restrict__ ln_g, const float* __restrict__ ln_b)
{
    __shared__ __align__(16) float sbuf[4][NREC];   // 4-deep token ring
    __shared__ float4 sxch[2][2][32];               // [parity][warp][lane]

    const int b    = blockIdx.x;
    const int tid  = threadIdx.x;
    const int warp = tid >> 5;
    const int lane = tid & 31;
    const int o0   = 2 * lane, o1 = o0 + 1;
    const int cb   = 32 * warp;                     // column base

    const float g0 = ln_g[o0], g1 = ln_g[o1];
    const float lb0 = ln_b[o0], lb1 = ln_b[o1];
    const float cc0 = g0 * g0, cc1 = g1 * g1;

    float Sc = cc0 + cc1;
#pragma unroll
    for (int off = 16; off; off >>= 1) Sc += __shfl_xor_sync(~0u, Sc, off);

    // W regs: this warp's 32 columns of rows o0,o1 (16 f32x2 each)
    ull w0[16], w1[16];
    {
        const float4* r0 = (const float4*)&W0[o0 * 64 + cb];
        const float4* r1 = (const float4*)&W0[o1 * 64 + cb];
#pragma unroll
        for (int j = 0; j < 8; j++) {
            float4 a = r0[j]; w0[2 * j] = pack2(a.x, a.y); w0[2 * j + 1] = pack2(a.z, a.w);
            float4 c = r1[j]; w1[2 * j] = pack2(c.x, c.y); w1[2 * j + 1] = pack2(c.z, c.w);
        }
    }

    const float4* p4 = (const float4*)(g_proj + (size_t)b * TT * NREC); // 64 f4/token
    float* hout = g_h + (size_t)b * TT * BD;

    // partial dot of both owned W rows with warp's column slice of vsrc
    auto mvh = [&](const float* vsrc, float& d0, float& d1) {
        ull A0 = 0, A1 = 0, B0 = 0, B1 = 0;
        const ulonglong2* vv2 = (const ulonglong2*)&vsrc[cb];
#pragma unroll
        for (int j = 0; j < 8; j++) {
            ulonglong2 vv = vv2[j];
            fma2(A0, w0[2 * j], vv.x); fma2(A1, w0[2 * j + 1], vv.y);
            fma2(B0, w1[2 * j], vv.x); fma2(B1, w1[2 * j + 1], vv.y);
        }
        float p, q, r, s;
        unpack2(A0, p, q); unpack2(A1, r, s); d0 = (p + q) + (r + s);
        unpack2(B0, p, q); unpack2(B1, r, s); d1 = (p + q) + (r + s);
    };
    auto updh = [&](const float* ksrc, float c0u, float c1u) {
        ull n0 = pack2(-c0u, -c0u), n1 = pack2(-c1u, -c1u);
        const ulonglong2* kk2 = (const ulonglong2*)&ksrc[cb];
#pragma unroll
        for (int j = 0; j < 8; j++) {
            ulonglong2 kk = kk2[j];
            fma2(w0[2 * j], n0, kk.x); fma2(w0[2 * j + 1], n0, kk.y);
            fma2(w1[2 * j], n1, kk.x); fma2(w1[2 * j + 1], n1, kk.y);
        }
    };

    // prologue: zero slot 3; tokens 0,1 -> slots 0,1 (64 threads, 1 f4 each)
    *(float4*)&sbuf[3][4 * tid] = make_float4(0.f, 0.f, 0.f, 0.f);
    *(float4*)&sbuf[0][4 * tid] = p4[tid];
    *(float4*)&sbuf[1][4 * tid] = p4[64 + tid];
    float4 pS = p4[128 + tid];    // token 2
    float4 pL = p4[192 + tid];    // token 3
    __syncthreads();

    // initial M, Mq for token 0 (partial + exchange, parity slot 1)
    float M0, M1, Mq0, Mq1;
    {
        float a0p, a1p, b0p, b1p;
        mvh(&sbuf[0][0],   a0p, a1p);
        mvh(&sbuf[0][128], b0p, b1p);
        sxch[1][warp][lane] = make_float4(a0p, a1p, b0p, b1p);
        __syncthreads();
        float4 oth = sxch[1][warp ^ 1][lane];
        M0 = a0p + oth.x; M1 = a1p + oth.y; Mq0 = b0p + oth.z; Mq1 = b1p + oth.w;
    }

    const float inv64 = 1.f / 64.f;
    const float twon  = 2.f / 64.f;
    const float mean_c = Sc * inv64;

    float cg0 = 0.f, cg1 = 0.f, Gkk = 0.f, Gkq = 0.f;
    float pZqn0 = 0.f, pZqn1 = 0.f, pq0 = 0.f, pq1 = 0.f;

    for (int t = 0; t < TT; t++) {
        const int cur = t & 3, nxt = (t + 1) & 3, prv = (t - 1) & 3, st2 = (t + 2) & 3;
        const float* kb = &sbuf[cur][0];

        // ring store token t+2 (1 f4 per thread), rotate, LDG token t+4
        if (t + 2 < TT) *(float4*)&sbuf[st2][4 * tid] = pS;
        pS = pL;
        if (t + 4 < TT) pL = p4[(size_t)(t + 4) * 64 + tid];

        // bulk: apply rank-1 of token t-1, lagged matvec partials for token t+1
        updh(&sbuf[prv][0], cg0, cg1);
        float pMn0, pMn1, pMqn0, pMqn1;
        mvh(&sbuf[nxt][0],   pMn0,  pMn1);
        mvh(&sbuf[nxt][128], pMqn0, pMqn1);

        // exchange partial dots (one bar per token; also orders ring stores)
        sxch[t & 1][warp][lane] = make_float4(pMn0, pMn1, pMqn0, pMqn1);
        __syncthreads();
        float4 oth = sxch[t & 1][warp ^ 1][lane];
        const float Mn0 = pMn0 + oth.x, Mn1 = pMn1 + oth.y;
        const float Mqn0 = pMqn0 + oth.z, Mqn1 = pMqn1 + oth.w;

        // Z_t = W_{t-1}·k_t via rank-1 correction
        const float Z0 = M0 - cg0 * Gkk;
        const float Z1 = M1 - cg1 * Gkk;

        // own entries of token t and t+1 (duplicated in both warps)
        float k0p, k1p, v0p, v1p, q0p, q1p, kn0, kn1, qn0, qn1;
        unpack2(*(const ull*)&kb[o0],        k0p, k1p);
        unpack2(*(const ull*)&kb[64 + o0],   v0p, v1p);
        unpack2(*(const ull*)&kb[128 + o0],  q0p, q1p);
        unpack2(*(const ull*)&sbuf[nxt][o0],       kn0, kn1);
        unpack2(*(const ull*)&sbuf[nxt][128 + o0], qn0, qn1);
        const float eta = kb[192];

        const float a0 = g0 * (k0p - v0p + lb0);
        const float a1 = g1 * (k1p - v1p + lb1);

        // 11-value butterfly (duplicated in both warps)
        float r0 = Z0 + Z1;
        float r1 = Z0 * Z0 + Z1 * Z1;
        float r2 = a0 * Z0 + a1 * Z1;
        float r3 = cc0 * Z0 + cc1 * Z1;
        float r4 = cc0 * Z0 * Z0 + cc1 * Z1 * Z1;
        float r5 = a0 + a1;
        float r6 = k0p * q0p + k1p * q1p;           // k_t·q_t
        float r7 = k0p * kn0 + k1p * kn1;           // k_t·k_{t+1}
        float r8 = k0p * qn0 + k1p * qn1;           // k_t·q_{t+1}
        float r9  = pZqn0 + pZqn1;                  // LN2 stats (token t-1)
        float r10 = pZqn0 * pZqn0 + pZqn1 * pZqn1;
#pragma unroll
        for (int off = 16; off; off >>= 1) {
            r0 += __shfl_xor_sync(~0u, r0, off);
            r1 += __shfl_xor_sync(~0u, r1, off);
            r2 += __shfl_xor_sync(~0u, r2, off);
            r3 += __shfl_xor_sync(~0u, r3, off);
            r4 += __shfl_xor_sync(~0u, r4, off);
            r5 += __shfl_xor_sync(~0u, r5, off);
            r6 += __shfl_xor_sync(~0u, r6, off);
            r7 += __shfl_xor_sync(~0u, r7, off);
            r8 += __shfl_xor_sync(~0u, r8, off);
            r9 += __shfl_xor_sync(~0u, r9, off);
            r10 += __shfl_xor_sync(~0u, r10, off);
        }

        const float mu  = r0 * inv64;
        const float var = r1 * inv64 - mu * mu;
        const float rs  = rsqrtf(var + 1e-6f);
        const float mean_aZ  = r2 * inv64;
        const float mean_cZ  = r3 * inv64;
        const float mean_cZ2 = r4 * inv64;
        const float mean_a   = r5 * inv64;
        const float kq       = r6;

        const float m1 = twon * (mean_a + rs * (mean_cZ - mu * mean_c));
        const float m2 = twon * (rs * (mean_aZ - mu * mean_a)
                        + rs * rs * (mean_cZ2 - 2.f * mu * mean_cZ + mu * mu * mean_c));
        const float zh0 = (Z0 - mu) * rs, zh1 = (Z1 - mu) * rs;
        const float gz0 = rs * (twon * (a0 + cc0 * zh0) - m1 - zh0 * m2);
        const float gz1 = rs * (twon * (a1 + cc1 * zh1) - m1 - zh1 * m2);
        const float coef0 = eta * gz0, coef1 = eta * gz1;

        // LN2 + store h for token t-1 (warp 0 stores)
        if (t > 0 && warp == 0) {
            const float mu2 = r9 * inv64;
            const float rs2 = rsqrtf(r10 * inv64 - mu2 * mu2 + 1e-6f);
            const float h0 = pq0 + (pZqn0 - mu2) * rs2 * g0 + lb0;
            const float h1 = pq1 + (pZqn1 - mu2) * rs2 * g1 + lb1;
            *(ull*)&hout[(size_t)(t - 1) * BD + o0] = pack2(h0, h1);
        }

        // Zq_t on W_t via corrections
        pZqn0 = (Mq0 - cg0 * Gkq) - coef0 * kq;
        pZqn1 = (Mq1 - cg1 * Gkq) - coef1 * kq;
        pq0 = q0p; pq1 = q1p;

        // carry
        cg0 = coef0; cg1 = coef1;
        Gkk = r7; Gkq = r8;
        M0 = Mn0; M1 = Mn1; Mq0 = Mqn0; Mq1 = Mqn1;
    }

    // final token LN2 + store
    if (warp == 0) {
        float s0 = pZqn0 + pZqn1;
        float s1 = pZqn0 * pZqn0 + pZqn1 * pZqn1;
#pragma unroll
        for (int off = 16; off; off >>= 1) {
            s0 += __shfl_xor_sync(~0u, s0, off);
            s1 += __shfl_xor_sync(~0u, s1, off);
        }
        float mu2 = s0 * inv64;
        float rs2 = rsqrtf(s1 * inv64 - mu2 * mu2 + 1e-6f);
        float h0 = pq0 + (pZqn0 - mu2) * rs2 * g0 + lb0;
        float h1 = pq1 + (pZqn1 - mu2) * rs2 * g1 + lb1;
        *(ull*)&hout[(size_t)(TT - 1) * BD + o0] = pack2(h0, h1);
    }
}

// ---------------------------------------------------------------------------
// Kernel 3: z = h @ Wo + bo.  M=32768, K=64, N=512. BM=128 (4 rows/thread),
// BN=64, 128 threads.
// ---------------------------------------------------------------------------
__global__ void __launch_bounds__(128) out_kernel(
    const float* __restrict__ Wo, const float* __restrict__ bo,
    float* __restrict__ z)
{
    __shared__ float sh[128][68];   // h tile, padded rows (f4-aligned)
    __shared__ float sw2[64][64];

    const int tid = threadIdx.x;
    const int mbase = blockIdx.x * 128;
    const int nbase = blockIdx.y * 64;
    const int m  = tid >> 2;        // 0..31 -> rows m, m+32, m+64, m+96
    const int ng = tid & 3;

    for (int i = tid; i < 2048; i += 128) {
        int row = i >> 4;
        int c = (i & 15) * 4;
        *(float4*)&sh[row][c] = *(const float4*)&g_h[(size_t)(mbase + row) * BD + c];
    }
    for (int i = tid; i < 1024; i += 128) {
        int row = i >> 4;
        int c = (i & 15) * 4;
        *(float4*)&sw2[row][c] = *(const float4*)&Wo[(size_t)row * DD + nbase + c];
    }
    __syncthreads();

    ull acc[4][8];
#pragma unroll
    for (int r = 0; r < 4; r++)
#pragma unroll
        for (int j = 0; j < 8; j++) acc[r][j] = 0ull;

#pragma unroll 4
    for (int kk = 0; kk < 16; kk++) {
        float hr[4][4];
#pragma unroll
        for (int r = 0; r < 4; r++)
            *(float4*)&hr[r][0] = *(const float4*)&sh[m + 32 * r][4 * kk];
#pragma unroll
        for (int dk = 0; dk < 4; dk++) {
            const int k = 4 * kk + dk;
            ull hp[4];
#pragma unroll
            for (int r = 0; r < 4; r++) hp[r] = pack2(hr[r][dk], hr[r][dk]);
#pragma unroll
            for (int j = 0; j < 4; j++) {
                ulonglong2 w2 = *(const ulonglong2*)&sw2[k][ng * 4 + 16 * j];
#pragma unroll
                for (int r = 0; r < 4; r++) {
                    fma2(acc[r][2 * j],     hp[r], w2.x);
                    fma2(acc[r][2 * j + 1], hp[r], w2.y);
                }
            }
        }
    }
#pragma unroll
    for (int r = 0; r < 4; r++) {
        float out[16];
#pragma unroll
        for (int j = 0; j < 8; j++) unpack2(acc[r][j], out[2 * j], out[2 * j + 1]);
        float* dstrow = &z[(size_t)(mbase + m + 32 * r) * DD];
#pragma unroll
        for (int j = 0; j < 4; j++) {
            int c = nbase + ng * 4 + 16 * j;
            float4 bv = *(const float4*)&bo[c];
            *(float4*)&dstrow[c] = make_float4(out[4 * j] + bv.x, out[4 * j + 1] + bv.y,
                                               out[4 * j + 2] + bv.z, out[4 * j + 3] + bv.w);
        }
    }
}

// ---------------------------------------------------------------------------
extern "C" void kernel_launch(void* const* d_in, const int* in_sizes, int n_in,
                              void* d_out, int out_size)
{
    const float* x    = (const float*)d_in[0];
    const float* Wk   = (const float*)d_in[1];
    const float* bk   = (const float*)d_in[2];
    const float* Wv   = (const float*)d_in[3];
    const float* bv   = (const float*)d_in[4];
    const float* Wq   = (const float*)d_in[5];
    const float* bq   = (const float*)d_in[6];
    const float* Wo   = (const float*)d_in[7];
    const float* bo   = (const float*)d_in[8];
    const float* ln_g = (const float*)d_in[9];
    const float* ln_b = (const float*)d_in[10];
    const float* lr_w = (const float*)d_in[11];
    const float* lr_b = (const float*)d_in[12];
    const float* W0   = (const float*)d_in[13];
    float* z = (float*)d_out;

    prep_kernel<<<448, 256>>>(Wk, Wv, Wq, lr_w, bk, bv, bq);
    proj_kernel<<<dim3(256, 2), 256>>>(x, lr_b);
    scan_kernel<<<BB, 64>>>(W0, ln_g, ln_b);
    out_kernel<<<dim3(256, 8), 128>>>(Wo, bo, z);
}